// round 1
// baseline (speedup 1.0000x reference)
#include <cuda_runtime.h>
#include <cuda_bf16.h>

#define NUM_SEG 32
#define C 256
#define C4 64   // float4 per row

// Scratch (allocation-free rule: __device__ globals)
__device__ float  g_sum[NUM_SEG * C];
__device__ float4 g_y4[NUM_SEG * C4];   // gates, float4-aligned

// ---------------------------------------------------------------------------
// Kernel 0: zero the accumulator (must re-run every launch: graph replays)
// ---------------------------------------------------------------------------
__global__ void se_zero_kernel() {
    int i = blockIdx.x * blockDim.x + threadIdx.x;
    if (i < NUM_SEG * C) g_sum[i] = 0.0f;
}

// ---------------------------------------------------------------------------
// Kernel 1: segment sum. Block owns ROWS_PER_BLOCK contiguous rows (sorted
// batch_idx => very few segment changes per block). 256 threads =
// 64 float4 channel lanes x 4 subrows. Register accumulation, atomic flush
// only on segment boundary.
// ---------------------------------------------------------------------------
#define ROWS_PER_BLOCK 512

__global__ void se_reduce_kernel(const float4* __restrict__ feats,
                                 const int*    __restrict__ idx,
                                 int N) {
    const int c4  = threadIdx.x & 63;   // channel float4 lane
    const int sub = threadIdx.x >> 6;   // 0..3
    long base = (long)blockIdx.x * ROWS_PER_BLOCK;
    long end  = base + ROWS_PER_BLOCK;
    if (end > N) end = N;

    float4 acc = make_float4(0.f, 0.f, 0.f, 0.f);
    int cur = -1;

    for (long r = base + sub; r < end; r += 4) {
        int s = idx[r];
        float4 v = feats[r * C4 + c4];
        if (s != cur) {
            if (cur >= 0) {
                float* dst = &g_sum[cur * C + c4 * 4];
                atomicAdd(dst + 0, acc.x);
                atomicAdd(dst + 1, acc.y);
                atomicAdd(dst + 2, acc.z);
                atomicAdd(dst + 3, acc.w);
            }
            cur = s;
            acc = v;
        } else {
            acc.x += v.x; acc.y += v.y; acc.z += v.z; acc.w += v.w;
        }
    }
    if (cur >= 0) {
        float* dst = &g_sum[cur * C + c4 * 4];
        atomicAdd(dst + 0, acc.x);
        atomicAdd(dst + 1, acc.y);
        atomicAdd(dst + 2, acc.z);
        atomicAdd(dst + 3, acc.w);
    }
}

// ---------------------------------------------------------------------------
// Kernel 2: counts (binary search on sorted idx) + mean + MLP + sigmoid.
// Single block, 256 threads. Total compute ~0.5 MFLOP — negligible.
// ---------------------------------------------------------------------------
__global__ void se_mlp_kernel(const int*   __restrict__ idx, int N,
                              const float* __restrict__ W1,
                              const float* __restrict__ b1,
                              const float* __restrict__ W2,
                              const float* __restrict__ b2) {
    __shared__ float s_pooled[NUM_SEG * C];   // 32 KB
    __shared__ float s_h[NUM_SEG * 16];
    __shared__ int   s_lb[NUM_SEG + 1];

    const int t = threadIdx.x;

    // lower_bound(idx, s) for s = 0..32
    if (t <= NUM_SEG) {
        int lo = 0, hi = N;
        while (lo < hi) {
            int mid = (lo + hi) >> 1;
            if (idx[mid] < t) lo = mid + 1; else hi = mid;
        }
        s_lb[t] = lo;
    }
    __syncthreads();

    // pooled = sum / max(count, 1)
    for (int i = t; i < NUM_SEG * C; i += 256) {
        int s = i >> 8;   // / C
        float cnt = (float)(s_lb[s + 1] - s_lb[s]);
        s_pooled[i] = g_sum[i] / fmaxf(cnt, 1.0f);
    }
    __syncthreads();

    // h = relu(pooled @ W1 + b1)   [32 x 16]
    for (int o = t; o < NUM_SEG * 16; o += 256) {
        int s = o >> 4;
        int j = o & 15;
        float accv = b1[j];
        const float* p = &s_pooled[s * C];
        #pragma unroll 8
        for (int k = 0; k < C; k++) accv += p[k] * W1[k * 16 + j];
        s_h[o] = fmaxf(accv, 0.0f);
    }
    __syncthreads();

    // y = sigmoid(h @ W2 + b2)   [32 x 256]
    float* y = (float*)g_y4;
    for (int o = t; o < NUM_SEG * C; o += 256) {
        int s = o >> 8;
        int j = o & 255;
        float accv = b2[j];
        const float* hh = &s_h[s * 16];
        #pragma unroll
        for (int k = 0; k < 16; k++) accv += hh[k] * W2[k * C + j];
        y[o] = 1.0f / (1.0f + __expf(-accv));
    }
}

// ---------------------------------------------------------------------------
// Kernel 3: out = feats * y[batch_idx].  Flat float4 grid-stride.
// idx (4MB) and gates (32KB) stay L1/L2 resident.
// ---------------------------------------------------------------------------
__global__ void se_scale_kernel(const float4* __restrict__ feats,
                                const int*    __restrict__ idx,
                                float4*       __restrict__ out,
                                long total4) {
    long stride = (long)gridDim.x * blockDim.x;
    for (long i = (long)blockIdx.x * blockDim.x + threadIdx.x;
         i < total4; i += stride) {
        int row = (int)(i >> 6);
        int c4  = (int)(i & 63);
        int s   = __ldg(&idx[row]);
        float4 v = feats[i];
        float4 g = g_y4[s * C4 + c4];
        float4 o;
        o.x = v.x * g.x; o.y = v.y * g.y; o.z = v.z * g.z; o.w = v.w * g.w;
        out[i] = o;
    }
}

// ---------------------------------------------------------------------------
extern "C" void kernel_launch(void* const* d_in, const int* in_sizes, int n_in,
                              void* d_out, int out_size) {
    const float* feats = (const float*)d_in[0];
    const int*   idx   = (const int*)  d_in[1];
    const float* W1    = (const float*)d_in[2];
    const float* b1    = (const float*)d_in[3];
    const float* W2    = (const float*)d_in[4];
    const float* b2    = (const float*)d_in[5];

    const int N = in_sizes[1];               // number of points
    const long total4 = (long)N * C4;

    se_zero_kernel<<<(NUM_SEG * C + 255) / 256, 256>>>();

    int rblocks = (N + ROWS_PER_BLOCK - 1) / ROWS_PER_BLOCK;
    se_reduce_kernel<<<rblocks, 256>>>((const float4*)feats, idx, N);

    se_mlp_kernel<<<1, 256>>>(idx, N, W1, b1, W2, b2);

    se_scale_kernel<<<2368, 256>>>((const float4*)feats, idx,
                                   (float4*)d_out, total4);
}